// round 1
// baseline (speedup 1.0000x reference)
#include <cuda_runtime.h>
#include <math.h>

#define NTOK 1024
#define DINV 512
#define NFV  4
#define NHV  8
#define HDV  64

// -------- scratch (device globals; no allocation allowed) --------
__device__ float g_cm[2][NFV][DINV];               // [qkv|proj][f][d]
__device__ float g_q[NHV * NFV * NTOK * HDV];      // [h][f][n][d], pre-scaled by hd^-0.5
__device__ float g_k[NHV * NFV * NTOK * HDV];
__device__ float g_v[NHV * NFV * NTOK * HDV];
__device__ float g_yhat[NFV * NTOK * DINV];        // [f][n][h*64+d]

// ============================================================
// K1: code_mod = LayerNorm((w_c @ code).T) * g + b, both variants
// ============================================================
__global__ __launch_bounds__(512) void code_mod_kernel(
    const float* __restrict__ wc, const float* __restrict__ code,
    const float* __restrict__ gq, const float* __restrict__ bq,
    const float* __restrict__ gp, const float* __restrict__ bp)
{
    int d = threadIdx.x;  // 0..511
    float t[NFV] = {0.f, 0.f, 0.f, 0.f};
    for (int k = 0; k < 128; k++) {
        float w = wc[d * 128 + k];
        #pragma unroll
        for (int f = 0; f < NFV; f++) t[f] += w * code[k * NFV + f];
    }
    __shared__ float red[512];
    float gqd = gq[d], bqd = bq[d], gpd = gp[d], bpd = bp[d];
    for (int f = 0; f < NFV; f++) {
        red[d] = t[f];
        __syncthreads();
        for (int s = 256; s > 0; s >>= 1) {
            if (d < s) red[d] += red[d + s];
            __syncthreads();
        }
        float mu = red[0] * (1.f / 512.f);
        __syncthreads();
        float dv = t[f] - mu;
        red[d] = dv * dv;
        __syncthreads();
        for (int s = 256; s > 0; s >>= 1) {
            if (d < s) red[d] += red[d + s];
            __syncthreads();
        }
        float var = red[0] * (1.f / 512.f);
        __syncthreads();
        float nrm = dv * rsqrtf(var + 1e-5f);
        g_cm[0][f][d] = nrm * gqd + bqd;
        g_cm[1][f][d] = nrm * gpd + bpd;
    }
}

// ============================================================
// K2/K4: SGEMM  C[m,n] = sum_k (A[m,k]*cm[f,k]) * Bw[n,k]  (+bias)
// MODE 0: A = x (shared over f), outputs scattered into q/k/v (q pre-scaled)
// MODE 1: A = yhat[f], output -> d_out[f]
// 128x128 tile, BK=16, 256 threads, 8x8 per-thread microtile.
// ============================================================
template <int MODE>
__global__ __launch_bounds__(256) void sgemm_kernel(
    const float* __restrict__ Ain, const float* __restrict__ Bw,
    const float* __restrict__ bias, float* __restrict__ Out)
{
    const int f = blockIdx.z;
    const float* A = (MODE == 0) ? Ain : (g_yhat + (size_t)f * NTOK * DINV);

    __shared__ float As[16][128];
    __shared__ float Bs[16][128];
    __shared__ float sc[512];

    int tid = threadIdx.x;
    sc[tid]       = g_cm[MODE][f][tid];
    sc[tid + 256] = g_cm[MODE][f][tid + 256];
    __syncthreads();

    int bm0 = blockIdx.y * 128;
    int bn0 = blockIdx.x * 128;
    int lrow = tid >> 1;           // 0..127
    int lk   = (tid & 1) * 8;      // 0 or 8
    const float* Ap = A  + (size_t)(bm0 + lrow) * 512 + lk;
    const float* Bp = Bw + (size_t)(bn0 + lrow) * 512 + lk;

    int ty = tid >> 4;             // 0..15
    int tx = tid & 15;             // 0..15

    float acc[8][8];
    #pragma unroll
    for (int i = 0; i < 8; i++)
        #pragma unroll
        for (int j = 0; j < 8; j++) acc[i][j] = 0.f;

    for (int k0 = 0; k0 < 512; k0 += 16) {
        float4 a0 = *(const float4*)(Ap + k0);
        float4 a1 = *(const float4*)(Ap + k0 + 4);
        float4 b0 = *(const float4*)(Bp + k0);
        float4 b1 = *(const float4*)(Bp + k0 + 4);
        As[lk + 0][lrow] = a0.x * sc[k0 + lk + 0];
        As[lk + 1][lrow] = a0.y * sc[k0 + lk + 1];
        As[lk + 2][lrow] = a0.z * sc[k0 + lk + 2];
        As[lk + 3][lrow] = a0.w * sc[k0 + lk + 3];
        As[lk + 4][lrow] = a1.x * sc[k0 + lk + 4];
        As[lk + 5][lrow] = a1.y * sc[k0 + lk + 5];
        As[lk + 6][lrow] = a1.z * sc[k0 + lk + 6];
        As[lk + 7][lrow] = a1.w * sc[k0 + lk + 7];
        Bs[lk + 0][lrow] = b0.x;
        Bs[lk + 1][lrow] = b0.y;
        Bs[lk + 2][lrow] = b0.z;
        Bs[lk + 3][lrow] = b0.w;
        Bs[lk + 4][lrow] = b1.x;
        Bs[lk + 5][lrow] = b1.y;
        Bs[lk + 6][lrow] = b1.z;
        Bs[lk + 7][lrow] = b1.w;
        __syncthreads();
        #pragma unroll
        for (int kk = 0; kk < 16; kk++) {
            float a[8], b[8];
            *(float4*)&a[0] = *(const float4*)&As[kk][ty * 8];
            *(float4*)&a[4] = *(const float4*)&As[kk][ty * 8 + 4];
            *(float4*)&b[0] = *(const float4*)&Bs[kk][tx * 8];
            *(float4*)&b[4] = *(const float4*)&Bs[kk][tx * 8 + 4];
            #pragma unroll
            for (int i = 0; i < 8; i++)
                #pragma unroll
                for (int j = 0; j < 8; j++) acc[i][j] += a[i] * b[j];
        }
        __syncthreads();
    }

    int j0 = bn0 + tx * 8;
    float bb[8];
    #pragma unroll
    for (int jj = 0; jj < 8; jj++) bb[jj] = bias[j0 + jj];

    if (MODE == 0) {
        int tt = j0 >> 9;                 // 0=q 1=k 2=v (tile never crosses)
        int h  = (j0 >> 6) & 7;
        int dd = j0 & 63;
        float* base = (tt == 0 ? g_q : tt == 1 ? g_k : g_v)
                      + (size_t)((h * NFV + f) * NTOK) * HDV + dd;
        float mul = (tt == 0) ? 0.125f : 1.0f;   // hd^-0.5 folded into q
        #pragma unroll
        for (int i = 0; i < 8; i++) {
            int m = bm0 + ty * 8 + i;
            float4 v0, v1;
            v0.x = (acc[i][0] + bb[0]) * mul;
            v0.y = (acc[i][1] + bb[1]) * mul;
            v0.z = (acc[i][2] + bb[2]) * mul;
            v0.w = (acc[i][3] + bb[3]) * mul;
            v1.x = (acc[i][4] + bb[4]) * mul;
            v1.y = (acc[i][5] + bb[5]) * mul;
            v1.z = (acc[i][6] + bb[6]) * mul;
            v1.w = (acc[i][7] + bb[7]) * mul;
            *(float4*)(base + (size_t)m * HDV)     = v0;
            *(float4*)(base + (size_t)m * HDV + 4) = v1;
        }
    } else {
        float* outp = Out + (size_t)f * NTOK * DINV;
        #pragma unroll
        for (int i = 0; i < 8; i++) {
            int m = bm0 + ty * 8 + i;
            float4 v0, v1;
            v0.x = acc[i][0] + bb[0];
            v0.y = acc[i][1] + bb[1];
            v0.z = acc[i][2] + bb[2];
            v0.w = acc[i][3] + bb[3];
            v1.x = acc[i][4] + bb[4];
            v1.y = acc[i][5] + bb[5];
            v1.z = acc[i][6] + bb[6];
            v1.w = acc[i][7] + bb[7];
            *(float4*)(outp + (size_t)m * 512 + j0)     = v0;
            *(float4*)(outp + (size_t)m * 512 + j0 + 4) = v1;
        }
    }
}

// ============================================================
// K3: attention, one block per (32-row block, h*f). Double softmax
// with compat modulation fused. Row-panel of scores lives in smem.
// smem floats: S 32768 | call 4096 | Qs 2080 | KV 8320 | crow 128 | inv2 32
// ============================================================
#define SM_CALL 32768
#define SM_QS   36864
#define SM_KV   38944
#define SM_CROW 47264
#define SM_INV2 47392
#define SM_FLOATS 47424

__global__ __launch_bounds__(256) void attn_kernel(const float* __restrict__ cin)
{
    extern __shared__ float sm[];
    float* S    = sm;
    float* call = sm + SM_CALL;
    float* Qs   = sm + SM_QS;
    float* KV   = sm + SM_KV;
    float* crow = sm + SM_CROW;
    float* inv2 = sm + SM_INV2;

    int tid = threadIdx.x;
    int n0  = blockIdx.x * 32;
    int hf  = blockIdx.y;           // h*4+f
    int h   = hf >> 2, f = hf & 3;
    size_t hb = (size_t)hf * NTOK * HDV;

    // load Q block (32x64, padded rows of 65)
    for (int i = tid; i < 512; i += 256) {
        int r = i >> 4, c4 = (i & 15) << 2;
        float4 v = *(const float4*)(g_q + hb + (size_t)(n0 + r) * HDV + c4);
        float* dst = &Qs[r * 65 + c4];
        dst[0] = v.x; dst[1] = v.y; dst[2] = v.z; dst[3] = v.w;
    }
    // full compatibility table [4][1024]
    for (int i = tid; i < 1024; i += 256)
        *(float4*)(call + 4 * i) = *(const float4*)(cin + 4 * i);
    // row-side compatibility
    if (tid < 128) crow[tid] = cin[(tid >> 5) * NTOK + n0 + (tid & 31)];
    __syncthreads();

    int wy = tid >> 5;   // warp 0..7 -> rows wy*4..wy*4+3
    int tx = tid & 31;   // lane -> cols tx + 32*j

    // ---- scores: S[r][m] = q[r]·k[m] (q pre-scaled) ----
    for (int mt = 0; mt < 8; mt++) {
        for (int i = tid; i < 2048; i += 256) {
            int r = i >> 4, c4 = (i & 15) << 2;
            float4 v = *(const float4*)(g_k + hb + (size_t)(mt * 128 + r) * HDV + c4);
            float* dst = &KV[r * 65 + c4];
            dst[0] = v.x; dst[1] = v.y; dst[2] = v.z; dst[3] = v.w;
        }
        __syncthreads();
        float acc[4][4];
        #pragma unroll
        for (int i = 0; i < 4; i++)
            #pragma unroll
            for (int j = 0; j < 4; j++) acc[i][j] = 0.f;
        #pragma unroll 4
        for (int d = 0; d < 64; d++) {
            float a0 = Qs[(wy * 4 + 0) * 65 + d];
            float a1 = Qs[(wy * 4 + 1) * 65 + d];
            float a2 = Qs[(wy * 4 + 2) * 65 + d];
            float a3 = Qs[(wy * 4 + 3) * 65 + d];
            float b0 = KV[(tx      ) * 65 + d];
            float b1 = KV[(tx + 32 ) * 65 + d];
            float b2 = KV[(tx + 64 ) * 65 + d];
            float b3 = KV[(tx + 96 ) * 65 + d];
            acc[0][0] += a0 * b0; acc[0][1] += a0 * b1; acc[0][2] += a0 * b2; acc[0][3] += a0 * b3;
            acc[1][0] += a1 * b0; acc[1][1] += a1 * b1; acc[1][2] += a1 * b2; acc[1][3] += a1 * b3;
            acc[2][0] += a2 * b0; acc[2][1] += a2 * b1; acc[2][2] += a2 * b2; acc[2][3] += a2 * b3;
            acc[3][0] += a3 * b0; acc[3][1] += a3 * b1; acc[3][2] += a3 * b2; acc[3][3] += a3 * b3;
        }
        #pragma unroll
        for (int i = 0; i < 4; i++)
            #pragma unroll
            for (int j = 0; j < 4; j++)
                S[(wy * 4 + i) * 1024 + mt * 128 + tx + 32 * j] = acc[i][j];
        __syncthreads();
    }

    // ---- double softmax with compat modulation (3 passes in smem) ----
    for (int rr = 0; rr < 4; rr++) {
        int r = wy * 4 + rr;
        float* Sr = S + r * 1024;
        float mx = -1e30f;
        for (int c = tx; c < 1024; c += 32) mx = fmaxf(mx, Sr[c]);
        #pragma unroll
        for (int o = 16; o; o >>= 1) mx = fmaxf(mx, __shfl_xor_sync(0xffffffffu, mx, o));
        float c0 = crow[r], c1 = crow[32 + r], c2 = crow[64 + r], c3 = crow[96 + r];
        float s1 = 0.f, um = 0.f;
        for (int c = tx; c < 1024; c += 32) {
            float e = __expf(Sr[c] - mx);
            float comp = c0 * call[c] + c1 * call[1024 + c]
                       + c2 * call[2048 + c] + c3 * call[3072 + c];
            float u = e * comp;                  // = attn*sum1*compat
            s1 += e; um = fmaxf(um, u);
            Sr[c] = u;
        }
        #pragma unroll
        for (int o = 16; o; o >>= 1) {
            s1 += __shfl_xor_sync(0xffffffffu, s1, o);
            um  = fmaxf(um, __shfl_xor_sync(0xffffffffu, um, o));
        }
        float inv1 = 1.f / s1;
        float m2   = um * inv1;                  // max of W_hat row
        float s2 = 0.f;
        for (int c = tx; c < 1024; c += 32) {
            float p = __expf(Sr[c] * inv1 - m2);
            s2 += p;
            Sr[c] = p;
        }
        #pragma unroll
        for (int o = 16; o; o >>= 1) s2 += __shfl_xor_sync(0xffffffffu, s2, o);
        if (tx == 0) inv2[r] = 1.f / s2;
    }
    __syncthreads();

    // ---- PV: O[r][d] = sum_m p[r][m] * v[m][d] ----
    float oacc[4][2];
    #pragma unroll
    for (int i = 0; i < 4; i++) { oacc[i][0] = 0.f; oacc[i][1] = 0.f; }
    for (int mt = 0; mt < 8; mt++) {
        for (int i = tid; i < 2048; i += 256) {
            int r = i >> 4, c4 = (i & 15) << 2;
            float4 v = *(const float4*)(g_v + hb + (size_t)(mt * 128 + r) * HDV + c4);
            float* dst = &KV[r * 65 + c4];
            dst[0] = v.x; dst[1] = v.y; dst[2] = v.z; dst[3] = v.w;
        }
        __syncthreads();
        #pragma unroll 2
        for (int m = 0; m < 128; m++) {
            float v0 = KV[m * 65 + tx];
            float v1 = KV[m * 65 + tx + 32];
            #pragma unroll
            for (int i = 0; i < 4; i++) {
                float s = S[(wy * 4 + i) * 1024 + mt * 128 + m];
                oacc[i][0] += s * v0;
                oacc[i][1] += s * v1;
            }
        }
        __syncthreads();
    }
    #pragma unroll
    for (int i = 0; i < 4; i++) {
        int r = wy * 4 + i;
        float is2 = inv2[r];
        float* yp = g_yhat + (size_t)f * NTOK * DINV + (size_t)(n0 + r) * DINV + h * HDV;
        yp[tx]      = oacc[i][0] * is2;
        yp[tx + 32] = oacc[i][1] * is2;
    }
}

// ============================================================
extern "C" void kernel_launch(void* const* d_in, const int* in_sizes, int n_in,
                              void* d_out, int out_size)
{
    const float* x      = (const float*)d_in[0];
    const float* compat = (const float*)d_in[1];
    const float* code   = (const float*)d_in[2];
    const float* wc     = (const float*)d_in[3];
    const float* Wqkv   = (const float*)d_in[4];
    const float* bqkv   = (const float*)d_in[5];
    const float* Wproj  = (const float*)d_in[6];
    const float* bproj  = (const float*)d_in[7];
    const float* lnqg   = (const float*)d_in[8];
    const float* lnqb   = (const float*)d_in[9];
    const float* lnpg   = (const float*)d_in[10];
    const float* lnpb   = (const float*)d_in[11];
    float* out = (float*)d_out;

    cudaFuncSetAttribute(attn_kernel,
                         cudaFuncAttributeMaxDynamicSharedMemorySize,
                         SM_FLOATS * 4);

    code_mod_kernel<<<1, 512>>>(wc, code, lnqg, lnqb, lnpg, lnpb);
    sgemm_kernel<0><<<dim3(12, 8, 4), 256>>>(x, Wqkv, bqkv, nullptr);
    attn_kernel<<<dim3(32, 32), 256, SM_FLOATS * 4>>>(compat);
    sgemm_kernel<1><<<dim3(4, 8, 4), 256>>>(nullptr, Wproj, bproj, out);
}

// round 3
// speedup vs baseline: 2.3325x; 2.3325x over previous
#include <cuda_runtime.h>
#include <math.h>
#include <stdint.h>

#define NTOK 1024
#define DINV 512
#define NFV  4
#define NHV  8
#define HDV  64

// -------- scratch (device globals; no allocation allowed) --------
__device__ float g_cm[2][NFV][DINV];               // [qkv|proj][f][d]
__device__ float g_q[NHV * NFV * NTOK * HDV];      // [h][f][n][d], pre-scaled by hd^-0.5
__device__ float g_k[NHV * NFV * NTOK * HDV];
__device__ float g_v[NHV * NFV * NTOK * HDV];
__device__ float g_yhat[NFV * NTOK * DINV];        // [f][n][h*64+d]

// ============================================================
// helpers: tf32 rounding + mma.sync (sm_80+ path, works at compute_103)
// ============================================================
__device__ __forceinline__ float to_tf32(float x) {
    uint32_t u;
    asm("cvt.rna.tf32.f32 %0, %1;" : "=r"(u) : "f"(x));
    return __uint_as_float(u);
}

__device__ __forceinline__ void mma_tf32(float* d, uint32_t a0, uint32_t a1,
                                         uint32_t a2, uint32_t a3,
                                         uint32_t b0, uint32_t b1) {
    asm volatile(
        "mma.sync.aligned.m16n8k8.row.col.f32.tf32.tf32.f32 "
        "{%0,%1,%2,%3}, {%4,%5,%6,%7}, {%8,%9}, {%0,%1,%2,%3};"
        : "+f"(d[0]), "+f"(d[1]), "+f"(d[2]), "+f"(d[3])
        : "r"(a0), "r"(a1), "r"(a2), "r"(a3), "r"(b0), "r"(b1));
}

// ============================================================
// K1: code_mod = LayerNorm((w_c @ code).T) * g + b, both variants
// ============================================================
__global__ __launch_bounds__(512) void code_mod_kernel(
    const float* __restrict__ wc, const float* __restrict__ code,
    const float* __restrict__ gq, const float* __restrict__ bq,
    const float* __restrict__ gp, const float* __restrict__ bp)
{
    int d = threadIdx.x;  // 0..511
    float t[NFV] = {0.f, 0.f, 0.f, 0.f};
    for (int k = 0; k < 128; k++) {
        float w = wc[d * 128 + k];
        #pragma unroll
        for (int f = 0; f < NFV; f++) t[f] += w * code[k * NFV + f];
    }
    __shared__ float red[512];
    float gqd = gq[d], bqd = bq[d], gpd = gp[d], bpd = bp[d];
    for (int f = 0; f < NFV; f++) {
        red[d] = t[f];
        __syncthreads();
        for (int s = 256; s > 0; s >>= 1) {
            if (d < s) red[d] += red[d + s];
            __syncthreads();
        }
        float mu = red[0] * (1.f / 512.f);
        __syncthreads();
        float dv = t[f] - mu;
        red[d] = dv * dv;
        __syncthreads();
        for (int s = 256; s > 0; s >>= 1) {
            if (d < s) red[d] += red[d + s];
            __syncthreads();
        }
        float var = red[0] * (1.f / 512.f);
        __syncthreads();
        float nrm = dv * rsqrtf(var + 1e-5f);
        g_cm[0][f][d] = nrm * gqd + bqd;
        g_cm[1][f][d] = nrm * gpd + bpd;
    }
}

// ============================================================
// tf32 mma GEMM: C[m,j] = sum_k (A[m,k]*cm[f,k]) * Bw[j,k] + bias[j]
// 128x128 tile, BK=32, double-buffered smem, 8 warps (2m x 4n).
// MODE 0: A = x, scatter -> g_q/g_k/g_v (q pre-scaled 0.125)
// MODE 1: A = g_yhat[f], out -> d_out
// smem floats: A0 0 | A1 4608 | B0 9216 | B1 13824 | SC 18432 | BIAS 18944
// ============================================================
#define GA0   0
#define GA1   4608
#define GB0   9216
#define GB1   13824
#define GSC   18432
#define GBIAS 18944
#define GEMM_SMEM_FLOATS 19072

template <int MODE>
__global__ __launch_bounds__(256) void gemm_mma(
    const float* __restrict__ Ain, const float* __restrict__ Bw,
    const float* __restrict__ bias, float* __restrict__ Out)
{
    extern __shared__ float sm[];
    const int f   = blockIdx.z;
    const int bm0 = blockIdx.y * 128;
    const int bn0 = blockIdx.x * 128;
    const int tid = threadIdx.x;
    const int warp = tid >> 5, lane = tid & 31;
    const int gid = lane >> 2, tig = lane & 3;
    const int wm = warp >> 2, wn = warp & 3;
    const float* A = (MODE == 0) ? Ain : (g_yhat + (size_t)f * NTOK * DINV);

    // scale + bias into smem
    sm[GSC + tid]       = g_cm[MODE][f][tid];
    sm[GSC + tid + 256] = g_cm[MODE][f][tid + 256];
    if (tid < 128) sm[GBIAS + tid] = bias[bn0 + tid];

    // staging map: row rb + 32*it, k4 within chunk
    const int rb = tid >> 3;
    const int k4 = (tid & 7) * 4;

    float4 ra[4], rbv[4];
    // LDG chunk 0
    #pragma unroll
    for (int it = 0; it < 4; it++) {
        ra[it]  = *(const float4*)(A  + (size_t)(bm0 + rb + 32 * it) * 512 + k4);
        rbv[it] = *(const float4*)(Bw + (size_t)(bn0 + rb + 32 * it) * 512 + k4);
    }
    __syncthreads();   // sc ready
    {
        float s0 = sm[GSC + k4], s1 = sm[GSC + k4 + 1],
              s2 = sm[GSC + k4 + 2], s3 = sm[GSC + k4 + 3];
        #pragma unroll
        for (int it = 0; it < 4; it++) {
            int row = rb + 32 * it;
            float* pa = sm + GA0 + row * 36 + k4;
            pa[0] = to_tf32(ra[it].x * s0); pa[1] = to_tf32(ra[it].y * s1);
            pa[2] = to_tf32(ra[it].z * s2); pa[3] = to_tf32(ra[it].w * s3);
            float* pb = sm + GB0 + row * 36 + k4;
            pb[0] = to_tf32(rbv[it].x); pb[1] = to_tf32(rbv[it].y);
            pb[2] = to_tf32(rbv[it].z); pb[3] = to_tf32(rbv[it].w);
        }
    }
    __syncthreads();

    float d[4][4][4];
    #pragma unroll
    for (int mt = 0; mt < 4; mt++)
        #pragma unroll
        for (int nt = 0; nt < 4; nt++)
            #pragma unroll
            for (int q = 0; q < 4; q++) d[mt][nt][q] = 0.f;

    for (int c = 0; c < 16; c++) {
        int cb = c & 1;
        if (c < 15) {
            int k0 = (c + 1) * 32;
            #pragma unroll
            for (int it = 0; it < 4; it++) {
                ra[it]  = *(const float4*)(A  + (size_t)(bm0 + rb + 32 * it) * 512 + k0 + k4);
                rbv[it] = *(const float4*)(Bw + (size_t)(bn0 + rb + 32 * it) * 512 + k0 + k4);
            }
        }
        const float* Ab = sm + (cb ? GA1 : GA0);
        const float* Bb = sm + (cb ? GB1 : GB0);
        #pragma unroll
        for (int kk = 0; kk < 4; kk++) {
            uint32_t aa[4][4], bb[4][2];
            #pragma unroll
            for (int mt = 0; mt < 4; mt++) {
                const float* p = Ab + (wm * 64 + mt * 16) * 36 + kk * 8;
                aa[mt][0] = __float_as_uint(p[gid * 36 + tig]);
                aa[mt][1] = __float_as_uint(p[(gid + 8) * 36 + tig]);
                aa[mt][2] = __float_as_uint(p[gid * 36 + tig + 4]);
                aa[mt][3] = __float_as_uint(p[(gid + 8) * 36 + tig + 4]);
            }
            #pragma unroll
            for (int nt = 0; nt < 4; nt++) {
                const float* p = Bb + (wn * 32 + nt * 8 + gid) * 36 + kk * 8;
                bb[nt][0] = __float_as_uint(p[tig]);
                bb[nt][1] = __float_as_uint(p[tig + 4]);
            }
            #pragma unroll
            for (int mt = 0; mt < 4; mt++)
                #pragma unroll
                for (int nt = 0; nt < 4; nt++)
                    mma_tf32(d[mt][nt], aa[mt][0], aa[mt][1], aa[mt][2], aa[mt][3],
                             bb[nt][0], bb[nt][1]);
        }
        __syncthreads();
        if (c < 15) {
            int k0 = (c + 1) * 32;
            float s0 = sm[GSC + k0 + k4], s1 = sm[GSC + k0 + k4 + 1],
                  s2 = sm[GSC + k0 + k4 + 2], s3 = sm[GSC + k0 + k4 + 3];
            float* Ad = sm + ((cb ^ 1) ? GA1 : GA0);
            float* Bd = sm + ((cb ^ 1) ? GB1 : GB0);
            #pragma unroll
            for (int it = 0; it < 4; it++) {
                int row = rb + 32 * it;
                float* pa = Ad + row * 36 + k4;
                pa[0] = to_tf32(ra[it].x * s0); pa[1] = to_tf32(ra[it].y * s1);
                pa[2] = to_tf32(ra[it].z * s2); pa[3] = to_tf32(ra[it].w * s3);
                float* pb = Bd + row * 36 + k4;
                pb[0] = to_tf32(rbv[it].x); pb[1] = to_tf32(rbv[it].y);
                pb[2] = to_tf32(rbv[it].z); pb[3] = to_tf32(rbv[it].w);
            }
            __syncthreads();
        }
    }

    // ---- epilogue ----
    const int jb = bn0 + wn * 32;        // 32-col strip, never crosses h/tt
    if (MODE == 0) {
        int tt = jb >> 9;
        int h  = (jb >> 6) & 7;
        int db = jb & 63;
        float mul = (tt == 0) ? 0.125f : 1.0f;
        float* base = (tt == 0 ? g_q : tt == 1 ? g_k : g_v)
                      + (size_t)((h * NFV + f) * NTOK) * HDV;
        #pragma unroll
        for (int mt = 0; mt < 4; mt++) {
            int m0 = bm0 + wm * 64 + mt * 16 + gid;
            #pragma unroll
            for (int nt = 0; nt < 4; nt++) {
                int dc = db + nt * 8 + tig * 2;
                float b0 = sm[GBIAS + wn * 32 + nt * 8 + tig * 2];
                float b1 = sm[GBIAS + wn * 32 + nt * 8 + tig * 2 + 1];
                float2 v0 = {(d[mt][nt][0] + b0) * mul, (d[mt][nt][1] + b1) * mul};
                float2 v1 = {(d[mt][nt][2] + b0) * mul, (d[mt][nt][3] + b1) * mul};
                *(float2*)(base + (size_t)m0 * HDV + dc)       = v0;
                *(float2*)(base + (size_t)(m0 + 8) * HDV + dc) = v1;
            }
        }
    } else {
        float* outp = Out + (size_t)f * NTOK * DINV;
        #pragma unroll
        for (int mt = 0; mt < 4; mt++) {
            int m0 = bm0 + wm * 64 + mt * 16 + gid;
            #pragma unroll
            for (int nt = 0; nt < 4; nt++) {
                int j = jb + nt * 8 + tig * 2;
                float b0 = sm[GBIAS + wn * 32 + nt * 8 + tig * 2];
                float b1 = sm[GBIAS + wn * 32 + nt * 8 + tig * 2 + 1];
                float2 v0 = {d[mt][nt][0] + b0, d[mt][nt][1] + b1};
                float2 v1 = {d[mt][nt][2] + b0, d[mt][nt][3] + b1};
                *(float2*)(outp + (size_t)m0 * 512 + j)       = v0;
                *(float2*)(outp + (size_t)(m0 + 8) * 512 + j) = v1;
            }
        }
    }
}

// ============================================================
// K3: attention with tf32 mma. One block per (32-row block, h*f).
// S panel stride 1036 (pad); Q stride 68; K view stride 68; V stride 72.
// smem floats: S 0 | CALL 33152 | QS 37248 | KV 39424 | CROW 48640 | INV2 48768
// ============================================================
#define SSTR    1036
#define AO_CALL 33152
#define AO_QS   37248
#define AO_KV   39424
#define AO_CROW 48640
#define AO_INV2 48768
#define ATTN_SMEM_FLOATS 48800

__global__ __launch_bounds__(256) void attn_kernel(const float* __restrict__ cin)
{
    extern __shared__ float sm[];
    float* S    = sm;
    float* call = sm + AO_CALL;
    float* Qs   = sm + AO_QS;
    float* KV   = sm + AO_KV;
    float* crow = sm + AO_CROW;
    float* inv2 = sm + AO_INV2;

    const int tid = threadIdx.x;
    const int warp = tid >> 5, lane = tid & 31;
    const int gid = lane >> 2, tig = lane & 3;
    const int n0  = blockIdx.x * 32;
    const int hf  = blockIdx.y;           // h*4+f
    const int h   = hf >> 2, f = hf & 3;
    const size_t hb = (size_t)hf * NTOK * HDV;

    // load Q block (32x64, stride 68), tf32-rounded
    for (int i = tid; i < 512; i += 256) {
        int r = i >> 4, c4 = (i & 15) << 2;
        float4 v = *(const float4*)(g_q + hb + (size_t)(n0 + r) * HDV + c4);
        float* dst = &Qs[r * 68 + c4];
        dst[0] = to_tf32(v.x); dst[1] = to_tf32(v.y);
        dst[2] = to_tf32(v.z); dst[3] = to_tf32(v.w);
    }
    for (int i = tid; i < 1024; i += 256)
        *(float4*)(call + 4 * i) = *(const float4*)(cin + 4 * i);
    if (tid < 128) crow[tid] = cin[(tid >> 5) * NTOK + n0 + (tid & 31)];
    __syncthreads();

    const int rg = warp & 1;          // row group (16 rows)
    const int cg = warp >> 1;         // col group for scores (32 of 128)

    // preload Q fragments for all 8 k-steps
    uint32_t aq0[8], aq1[8], aq2[8], aq3[8];
    {
        const float* q0 = Qs + (rg * 16 + gid) * 68;
        const float* q1 = Qs + (rg * 16 + gid + 8) * 68;
        #pragma unroll
        for (int k0 = 0; k0 < 8; k0++) {
            aq0[k0] = __float_as_uint(q0[k0 * 8 + tig]);
            aq1[k0] = __float_as_uint(q1[k0 * 8 + tig]);
            aq2[k0] = __float_as_uint(q0[k0 * 8 + tig + 4]);
            aq3[k0] = __float_as_uint(q1[k0 * 8 + tig + 4]);
        }
    }

    // ---- scores: S[r][m] = q[r]·k[m] (q pre-scaled) ----
    for (int mt = 0; mt < 8; mt++) {
        __syncthreads();
        for (int i = tid; i < 2048; i += 256) {
            int r = i >> 4, c4 = (i & 15) << 2;
            float4 v = *(const float4*)(g_k + hb + (size_t)(mt * 128 + r) * HDV + c4);
            float* dst = &KV[r * 68 + c4];
            dst[0] = to_tf32(v.x); dst[1] = to_tf32(v.y);
            dst[2] = to_tf32(v.z); dst[3] = to_tf32(v.w);
        }
        __syncthreads();
        float sacc[4][4];
        #pragma unroll
        for (int nt = 0; nt < 4; nt++)
            #pragma unroll
            for (int q = 0; q < 4; q++) sacc[nt][q] = 0.f;
        #pragma unroll
        for (int k0 = 0; k0 < 8; k0++) {
            #pragma unroll
            for (int nt = 0; nt < 4; nt++) {
                const float* p = KV + (cg * 32 + nt * 8 + gid) * 68 + k0 * 8;
                uint32_t b0 = __float_as_uint(p[tig]);
                uint32_t b1 = __float_as_uint(p[tig + 4]);
                mma_tf32(sacc[nt], aq0[k0], aq1[k0], aq2[k0], aq3[k0], b0, b1);
            }
        }
        int row0 = rg * 16 + gid;
        #pragma unroll
        for (int nt = 0; nt < 4; nt++) {
            int col = mt * 128 + cg * 32 + nt * 8 + tig * 2;
            *(float2*)&S[row0 * SSTR + col]       = make_float2(sacc[nt][0], sacc[nt][1]);
            *(float2*)&S[(row0 + 8) * SSTR + col] = make_float2(sacc[nt][2], sacc[nt][3]);
        }
    }
    __syncthreads();

    // ---- double softmax with compat modulation ----
    {
        int wy = warp, tx = lane;
        for (int rr = 0; rr < 4; rr++) {
            int r = wy * 4 + rr;
            float* Sr = S + r * SSTR;
            float mx = -1e30f;
            for (int c = tx; c < 1024; c += 32) mx = fmaxf(mx, Sr[c]);
            #pragma unroll
            for (int o = 16; o; o >>= 1) mx = fmaxf(mx, __shfl_xor_sync(0xffffffffu, mx, o));
            float c0 = crow[r], c1 = crow[32 + r], c2 = crow[64 + r], c3 = crow[96 + r];
            float s1 = 0.f, um = 0.f;
            for (int c = tx; c < 1024; c += 32) {
                float e = __expf(Sr[c] - mx);
                float comp = c0 * call[c] + c1 * call[1024 + c]
                           + c2 * call[2048 + c] + c3 * call[3072 + c];
                float u = e * comp;
                s1 += e; um = fmaxf(um, u);
                Sr[c] = u;
            }
            #pragma unroll
            for (int o = 16; o; o >>= 1) {
                s1 += __shfl_xor_sync(0xffffffffu, s1, o);
                um  = fmaxf(um, __shfl_xor_sync(0xffffffffu, um, o));
            }
            float inv1 = 1.f / s1;
            float m2   = um * inv1;
            float s2 = 0.f;
            for (int c = tx; c < 1024; c += 32) {
                float p = __expf(Sr[c] * inv1 - m2);
                s2 += p;
                Sr[c] = to_tf32(p);
            }
            #pragma unroll
            for (int o = 16; o; o >>= 1) s2 += __shfl_xor_sync(0xffffffffu, s2, o);
            if (tx == 0) inv2[r] = 1.f / s2;
        }
    }
    __syncthreads();

    // ---- PV: O[r][d] = sum_m p[r][m] * v[m][d] ----
    const int cg2 = warp >> 1;        // 4 col groups of 16 over 64 dims
    float o[2][4];
    #pragma unroll
    for (int nt = 0; nt < 2; nt++)
        #pragma unroll
        for (int q = 0; q < 4; q++) o[nt][q] = 0.f;

    for (int mt = 0; mt < 8; mt++) {
        __syncthreads();
        for (int i = tid; i < 2048; i += 256) {
            int r = i >> 4, c4 = (i & 15) << 2;
            float4 v = *(const float4*)(g_v + hb + (size_t)(mt * 128 + r) * HDV + c4);
            float* dst = &KV[r * 72 + c4];
            dst[0] = to_tf32(v.x); dst[1] = to_tf32(v.y);
            dst[2] = to_tf32(v.z); dst[3] = to_tf32(v.w);
        }
        __syncthreads();
        const float* Sr0 = S + (rg * 16 + gid) * SSTR + mt * 128;
        const float* Sr1 = Sr0 + 8 * SSTR;
        #pragma unroll
        for (int k0 = 0; k0 < 16; k0++) {
            uint32_t a0 = __float_as_uint(Sr0[k0 * 8 + tig]);
            uint32_t a1 = __float_as_uint(Sr1[k0 * 8 + tig]);
            uint32_t a2 = __float_as_uint(Sr0[k0 * 8 + tig + 4]);
            uint32_t a3 = __float_as_uint(Sr1[k0 * 8 + tig + 4]);
            #pragma unroll
            for (int nt = 0; nt < 2; nt++) {
                const float* p = KV + (k0 * 8 + tig) * 72 + cg2 * 16 + nt * 8 + gid;
                uint32_t b0 = __float_as_uint(p[0]);
                uint32_t b1 = __float_as_uint(p[4 * 72]);
                mma_tf32(o[nt], a0, a1, a2, a3, b0, b1);
            }
        }
    }

    // epilogue: scale by inv2 and scatter to g_yhat
    {
        int r0 = rg * 16 + gid;
        float isa = inv2[r0], isb = inv2[r0 + 8];
        float* yp0 = g_yhat + (size_t)f * NTOK * DINV + (size_t)(n0 + r0) * DINV + h * HDV;
        float* yp1 = g_yhat + (size_t)f * NTOK * DINV + (size_t)(n0 + r0 + 8) * DINV + h * HDV;
        #pragma unroll
        for (int nt = 0; nt < 2; nt++) {
            int dc = cg2 * 16 + nt * 8 + tig * 2;
            *(float2*)(yp0 + dc) = make_float2(o[nt][0] * isa, o[nt][1] * isa);
            *(float2*)(yp1 + dc) = make_float2(o[nt][2] * isb, o[nt][3] * isb);
        }
    }
}

// ============================================================
extern "C" void kernel_launch(void* const* d_in, const int* in_sizes, int n_in,
                              void* d_out, int out_size)
{
    const float* x      = (const float*)d_in[0];
    const float* compat = (const float*)d_in[1];
    const float* code   = (const float*)d_in[2];
    const float* wc     = (const float*)d_in[3];
    const float* Wqkv   = (const float*)d_in[4];
    const float* bqkv   = (const float*)d_in[5];
    const float* Wproj  = (const float*)d_in[6];
    const float* bproj  = (const float*)d_in[7];
    const float* lnqg   = (const float*)d_in[8];
    const float* lnqb   = (const float*)d_in[9];
    const float* lnpg   = (const float*)d_in[10];
    const float* lnpb   = (const float*)d_in[11];
    float* out = (float*)d_out;

    cudaFuncSetAttribute(attn_kernel,
                         cudaFuncAttributeMaxDynamicSharedMemorySize, ATTN_SMEM_FLOATS * 4);
    cudaFuncSetAttribute(gemm_mma<0>,
                         cudaFuncAttributeMaxDynamicSharedMemorySize, GEMM_SMEM_FLOATS * 4);
    cudaFuncSetAttribute(gemm_mma<1>,
                         cudaFuncAttributeMaxDynamicSharedMemorySize, GEMM_SMEM_FLOATS * 4);

    code_mod_kernel<<<1, 512>>>(wc, code, lnqg, lnqb, lnpg, lnpb);
    gemm_mma<0><<<dim3(12, 8, 4), 256, GEMM_SMEM_FLOATS * 4>>>(x, Wqkv, bqkv, nullptr);
    attn_kernel<<<dim3(32, 32), 256, ATTN_SMEM_FLOATS * 4>>>(compat);
    gemm_mma<1><<<dim3(4, 8, 4), 256, GEMM_SMEM_FLOATS * 4>>>(nullptr, Wproj, bproj, out);
}

// round 4
// speedup vs baseline: 2.7089x; 1.1614x over previous
#include <cuda_runtime.h>
#include <math.h>
#include <stdint.h>

#define NTOK 1024
#define DINV 512
#define NFV  4
#define NHV  8
#define HDV  64

// -------- scratch (device globals; no allocation allowed) --------
__device__ float g_cm[2][NFV][DINV];               // [qkv|proj][f][d]
__device__ float g_q[NHV * NFV * NTOK * HDV];      // [h][f][n][d], tf32, pre-scaled hd^-0.5
__device__ float g_k[NHV * NFV * NTOK * HDV];      // tf32
__device__ float g_v[NHV * NFV * NTOK * HDV];      // tf32
__device__ float g_yhat[NFV * NTOK * DINV];        // [f][n][h*64+d]
__device__ float g_callT[NTOK * NFV];              // [c][f] transposed compat

// ============================================================
// helpers
// ============================================================
__device__ __forceinline__ float to_tf32(float x) {
    uint32_t u;
    asm("cvt.rna.tf32.f32 %0, %1;" : "=r"(u) : "f"(x));
    return __uint_as_float(u);
}

__device__ __forceinline__ void mma_tf32(float* d, uint32_t a0, uint32_t a1,
                                         uint32_t a2, uint32_t a3,
                                         uint32_t b0, uint32_t b1) {
    asm volatile(
        "mma.sync.aligned.m16n8k8.row.col.f32.tf32.tf32.f32 "
        "{%0,%1,%2,%3}, {%4,%5,%6,%7}, {%8,%9}, {%0,%1,%2,%3};"
        : "+f"(d[0]), "+f"(d[1]), "+f"(d[2]), "+f"(d[3])
        : "r"(a0), "r"(a1), "r"(a2), "r"(a3), "r"(b0), "r"(b1));
}

__device__ __forceinline__ uint32_t smem_u32(const void* p) {
    uint32_t a;
    asm("{ .reg .u64 t; cvta.to.shared.u64 t, %1; cvt.u32.u64 %0, t; }" : "=r"(a) : "l"(p));
    return a;
}

__device__ __forceinline__ void cp_async16(uint32_t dst, const void* src) {
    asm volatile("cp.async.cg.shared.global [%0], [%1], 16;" :: "r"(dst), "l"(src) : "memory");
}
#define CP_COMMIT() asm volatile("cp.async.commit_group;" ::: "memory")
#define CP_WAIT0()  asm volatile("cp.async.wait_group 0;" ::: "memory")
#define CP_WAIT1()  asm volatile("cp.async.wait_group 1;" ::: "memory")

// stage one 128x64 fp32 tile into smem with row stride 68 (16B chunks)
__device__ __forceinline__ void stage_kv(uint32_t dstbase, const float* src, int tid) {
    #pragma unroll
    for (int i = tid; i < 2048; i += 256) {
        int row = i >> 4, c4 = (i & 15) << 2;
        cp_async16(dstbase + (uint32_t)(row * 68 + c4) * 4, src + row * 64 + c4);
    }
}

// ============================================================
// K1: code_mod = LayerNorm((w_c @ code).T) * g + b, both variants
// ============================================================
__global__ __launch_bounds__(512) void code_mod_kernel(
    const float* __restrict__ wc, const float* __restrict__ code,
    const float* __restrict__ gq, const float* __restrict__ bq,
    const float* __restrict__ gp, const float* __restrict__ bp)
{
    int d = threadIdx.x;
    float t[NFV] = {0.f, 0.f, 0.f, 0.f};
    for (int k = 0; k < 128; k++) {
        float w = wc[d * 128 + k];
        #pragma unroll
        for (int f = 0; f < NFV; f++) t[f] += w * code[k * NFV + f];
    }
    __shared__ float red[512];
    float gqd = gq[d], bqd = bq[d], gpd = gp[d], bpd = bp[d];
    for (int f = 0; f < NFV; f++) {
        red[d] = t[f];
        __syncthreads();
        for (int s = 256; s > 0; s >>= 1) {
            if (d < s) red[d] += red[d + s];
            __syncthreads();
        }
        float mu = red[0] * (1.f / 512.f);
        __syncthreads();
        float dv = t[f] - mu;
        red[d] = dv * dv;
        __syncthreads();
        for (int s = 256; s > 0; s >>= 1) {
            if (d < s) red[d] += red[d + s];
            __syncthreads();
        }
        float var = red[0] * (1.f / 512.f);
        __syncthreads();
        float nrm = dv * rsqrtf(var + 1e-5f);
        g_cm[0][f][d] = nrm * gqd + bqd;
        g_cm[1][f][d] = nrm * gpd + bpd;
    }
}

// tiny: transpose compat into [c][f]
__global__ __launch_bounds__(256) void prep_callT(const float* __restrict__ cin) {
    int c = blockIdx.x * 256 + threadIdx.x;
    float4 v = make_float4(cin[c], cin[NTOK + c], cin[2 * NTOK + c], cin[3 * NTOK + c]);
    *(float4*)&g_callT[c * 4] = v;
}

// ============================================================
// QKV GEMM (128x128 tile, BK=32, tf32 mma): outputs tf32-rounded q/k/v
// ============================================================
#define GA0   0
#define GA1   4608
#define GB0   9216
#define GB1   13824
#define GSC   18432
#define GBIAS 18944
#define GEMM_SMEM_FLOATS 19072

__global__ __launch_bounds__(256) void gemm_qkv(
    const float* __restrict__ Ain, const float* __restrict__ Bw,
    const float* __restrict__ bias)
{
    extern __shared__ float sm[];
    const int f   = blockIdx.z;
    const int bm0 = blockIdx.y * 128;
    const int bn0 = blockIdx.x * 128;
    const int tid = threadIdx.x;
    const int warp = tid >> 5, lane = tid & 31;
    const int gid = lane >> 2, tig = lane & 3;
    const int wm = warp >> 2, wn = warp & 3;
    const float* A = Ain;

    sm[GSC + tid]       = g_cm[0][f][tid];
    sm[GSC + tid + 256] = g_cm[0][f][tid + 256];
    if (tid < 128) sm[GBIAS + tid] = bias[bn0 + tid];

    const int rb = tid >> 3;
    const int k4 = (tid & 7) * 4;

    float4 ra[4], rbv[4];
    #pragma unroll
    for (int it = 0; it < 4; it++) {
        ra[it]  = *(const float4*)(A  + (size_t)(bm0 + rb + 32 * it) * 512 + k4);
        rbv[it] = *(const float4*)(Bw + (size_t)(bn0 + rb + 32 * it) * 512 + k4);
    }
    __syncthreads();
    {
        float s0 = sm[GSC + k4], s1 = sm[GSC + k4 + 1],
              s2 = sm[GSC + k4 + 2], s3 = sm[GSC + k4 + 3];
        #pragma unroll
        for (int it = 0; it < 4; it++) {
            int row = rb + 32 * it;
            float* pa = sm + GA0 + row * 36 + k4;
            pa[0] = to_tf32(ra[it].x * s0); pa[1] = to_tf32(ra[it].y * s1);
            pa[2] = to_tf32(ra[it].z * s2); pa[3] = to_tf32(ra[it].w * s3);
            float* pb = sm + GB0 + row * 36 + k4;
            pb[0] = to_tf32(rbv[it].x); pb[1] = to_tf32(rbv[it].y);
            pb[2] = to_tf32(rbv[it].z); pb[3] = to_tf32(rbv[it].w);
        }
    }
    __syncthreads();

    float d[4][4][4];
    #pragma unroll
    for (int mt = 0; mt < 4; mt++)
        #pragma unroll
        for (int nt = 0; nt < 4; nt++)
            #pragma unroll
            for (int q = 0; q < 4; q++) d[mt][nt][q] = 0.f;

    for (int c = 0; c < 16; c++) {
        int cb = c & 1;
        if (c < 15) {
            int k0 = (c + 1) * 32;
            #pragma unroll
            for (int it = 0; it < 4; it++) {
                ra[it]  = *(const float4*)(A  + (size_t)(bm0 + rb + 32 * it) * 512 + k0 + k4);
                rbv[it] = *(const float4*)(Bw + (size_t)(bn0 + rb + 32 * it) * 512 + k0 + k4);
            }
        }
        const float* Ab = sm + (cb ? GA1 : GA0);
        const float* Bb = sm + (cb ? GB1 : GB0);
        #pragma unroll
        for (int kk = 0; kk < 4; kk++) {
            uint32_t aa[4][4], bb[4][2];
            #pragma unroll
            for (int mt = 0; mt < 4; mt++) {
                const float* p = Ab + (wm * 64 + mt * 16) * 36 + kk * 8;
                aa[mt][0] = __float_as_uint(p[gid * 36 + tig]);
                aa[mt][1] = __float_as_uint(p[(gid + 8) * 36 + tig]);
                aa[mt][2] = __float_as_uint(p[gid * 36 + tig + 4]);
                aa[mt][3] = __float_as_uint(p[(gid + 8) * 36 + tig + 4]);
            }
            #pragma unroll
            for (int nt = 0; nt < 4; nt++) {
                const float* p = Bb + (wn * 32 + nt * 8 + gid) * 36 + kk * 8;
                bb[nt][0] = __float_as_uint(p[tig]);
                bb[nt][1] = __float_as_uint(p[tig + 4]);
            }
            #pragma unroll
            for (int mt = 0; mt < 4; mt++)
                #pragma unroll
                for (int nt = 0; nt < 4; nt++)
                    mma_tf32(d[mt][nt], aa[mt][0], aa[mt][1], aa[mt][2], aa[mt][3],
                             bb[nt][0], bb[nt][1]);
        }
        __syncthreads();
        if (c < 15) {
            int k0 = (c + 1) * 32;
            float s0 = sm[GSC + k0 + k4], s1 = sm[GSC + k0 + k4 + 1],
                  s2 = sm[GSC + k0 + k4 + 2], s3 = sm[GSC + k0 + k4 + 3];
            float* Ad = sm + ((cb ^ 1) ? GA1 : GA0);
            float* Bd = sm + ((cb ^ 1) ? GB1 : GB0);
            #pragma unroll
            for (int it = 0; it < 4; it++) {
                int row = rb + 32 * it;
                float* pa = Ad + row * 36 + k4;
                pa[0] = to_tf32(ra[it].x * s0); pa[1] = to_tf32(ra[it].y * s1);
                pa[2] = to_tf32(ra[it].z * s2); pa[3] = to_tf32(ra[it].w * s3);
                float* pb = Bd + row * 36 + k4;
                pb[0] = to_tf32(rbv[it].x); pb[1] = to_tf32(rbv[it].y);
                pb[2] = to_tf32(rbv[it].z); pb[3] = to_tf32(rbv[it].w);
            }
            __syncthreads();
        }
    }

    // epilogue: tf32-rounded scatter into q/k/v
    const int jb = bn0 + wn * 32;
    int tt = jb >> 9;
    int h  = (jb >> 6) & 7;
    int db = jb & 63;
    float mul = (tt == 0) ? 0.125f : 1.0f;
    float* base = (tt == 0 ? g_q : tt == 1 ? g_k : g_v)
                  + (size_t)((h * NFV + f) * NTOK) * HDV;
    #pragma unroll
    for (int mt = 0; mt < 4; mt++) {
        int m0 = bm0 + wm * 64 + mt * 16 + gid;
        #pragma unroll
        for (int nt = 0; nt < 4; nt++) {
            int dc = db + nt * 8 + tig * 2;
            float b0 = sm[GBIAS + wn * 32 + nt * 8 + tig * 2];
            float b1 = sm[GBIAS + wn * 32 + nt * 8 + tig * 2 + 1];
            float2 v0 = {to_tf32((d[mt][nt][0] + b0) * mul), to_tf32((d[mt][nt][1] + b1) * mul)};
            float2 v1 = {to_tf32((d[mt][nt][2] + b0) * mul), to_tf32((d[mt][nt][3] + b1) * mul)};
            *(float2*)(base + (size_t)m0 * HDV + dc)       = v0;
            *(float2*)(base + (size_t)(m0 + 8) * HDV + dc) = v1;
        }
    }
}

// ============================================================
// proj GEMM: 64x128 tile, 2 blocks/SM for load/MMA overlap
// ============================================================
#define H64_A0   0
#define H64_A1   2304
#define H64_B0   4608
#define H64_B1   9216
#define H64_SC   13824
#define H64_BIAS 14336
#define H64_FLOATS 14464

__global__ __launch_bounds__(256, 2) void gemm_proj(
    const float* __restrict__ Bw, const float* __restrict__ bias,
    float* __restrict__ Out)
{
    extern __shared__ float sm[];
    const int f   = blockIdx.z;
    const int bm0 = blockIdx.y * 64;
    const int bn0 = blockIdx.x * 128;
    const int tid = threadIdx.x;
    const int warp = tid >> 5, lane = tid & 31;
    const int gid = lane >> 2, tig = lane & 3;
    const int wm = warp >> 2, wn = warp & 3;
    const float* A = g_yhat + (size_t)f * NTOK * DINV;

    sm[H64_SC + tid]       = g_cm[1][f][tid];
    sm[H64_SC + tid + 256] = g_cm[1][f][tid + 256];
    if (tid < 128) sm[H64_BIAS + tid] = bias[bn0 + tid];

    const int rb = tid >> 3;
    const int k4 = (tid & 7) * 4;

    float4 ra[2], rbv[4];
    #pragma unroll
    for (int it = 0; it < 2; it++)
        ra[it] = *(const float4*)(A + (size_t)(bm0 + rb + 32 * it) * 512 + k4);
    #pragma unroll
    for (int it = 0; it < 4; it++)
        rbv[it] = *(const float4*)(Bw + (size_t)(bn0 + rb + 32 * it) * 512 + k4);
    __syncthreads();
    {
        float s0 = sm[H64_SC + k4], s1 = sm[H64_SC + k4 + 1],
              s2 = sm[H64_SC + k4 + 2], s3 = sm[H64_SC + k4 + 3];
        #pragma unroll
        for (int it = 0; it < 2; it++) {
            float* pa = sm + H64_A0 + (rb + 32 * it) * 36 + k4;
            pa[0] = to_tf32(ra[it].x * s0); pa[1] = to_tf32(ra[it].y * s1);
            pa[2] = to_tf32(ra[it].z * s2); pa[3] = to_tf32(ra[it].w * s3);
        }
        #pragma unroll
        for (int it = 0; it < 4; it++) {
            float* pb = sm + H64_B0 + (rb + 32 * it) * 36 + k4;
            pb[0] = to_tf32(rbv[it].x); pb[1] = to_tf32(rbv[it].y);
            pb[2] = to_tf32(rbv[it].z); pb[3] = to_tf32(rbv[it].w);
        }
    }
    __syncthreads();

    float d[2][4][4];
    #pragma unroll
    for (int mt = 0; mt < 2; mt++)
        #pragma unroll
        for (int nt = 0; nt < 4; nt++)
            #pragma unroll
            for (int q = 0; q < 4; q++) d[mt][nt][q] = 0.f;

    for (int c = 0; c < 16; c++) {
        int cb = c & 1;
        if (c < 15) {
            int k0 = (c + 1) * 32;
            #pragma unroll
            for (int it = 0; it < 2; it++)
                ra[it] = *(const float4*)(A + (size_t)(bm0 + rb + 32 * it) * 512 + k0 + k4);
            #pragma unroll
            for (int it = 0; it < 4; it++)
                rbv[it] = *(const float4*)(Bw + (size_t)(bn0 + rb + 32 * it) * 512 + k0 + k4);
        }
        const float* Ab = sm + (cb ? H64_A1 : H64_A0);
        const float* Bb = sm + (cb ? H64_B1 : H64_B0);
        #pragma unroll
        for (int kk = 0; kk < 4; kk++) {
            uint32_t aa[2][4], bb[4][2];
            #pragma unroll
            for (int mt = 0; mt < 2; mt++) {
                const float* p = Ab + (wm * 32 + mt * 16) * 36 + kk * 8;
                aa[mt][0] = __float_as_uint(p[gid * 36 + tig]);
                aa[mt][1] = __float_as_uint(p[(gid + 8) * 36 + tig]);
                aa[mt][2] = __float_as_uint(p[gid * 36 + tig + 4]);
                aa[mt][3] = __float_as_uint(p[(gid + 8) * 36 + tig + 4]);
            }
            #pragma unroll
            for (int nt = 0; nt < 4; nt++) {
                const float* p = Bb + (wn * 32 + nt * 8 + gid) * 36 + kk * 8;
                bb[nt][0] = __float_as_uint(p[tig]);
                bb[nt][1] = __float_as_uint(p[tig + 4]);
            }
            #pragma unroll
            for (int mt = 0; mt < 2; mt++)
                #pragma unroll
                for (int nt = 0; nt < 4; nt++)
                    mma_tf32(d[mt][nt], aa[mt][0], aa[mt][1], aa[mt][2], aa[mt][3],
                             bb[nt][0], bb[nt][1]);
        }
        __syncthreads();
        if (c < 15) {
            int k0 = (c + 1) * 32;
            float s0 = sm[H64_SC + k0 + k4], s1 = sm[H64_SC + k0 + k4 + 1],
                  s2 = sm[H64_SC + k0 + k4 + 2], s3 = sm[H64_SC + k0 + k4 + 3];
            float* Ad = sm + ((cb ^ 1) ? H64_A1 : H64_A0);
            float* Bd = sm + ((cb ^ 1) ? H64_B1 : H64_B0);
            #pragma unroll
            for (int it = 0; it < 2; it++) {
                float* pa = Ad + (rb + 32 * it) * 36 + k4;
                pa[0] = to_tf32(ra[it].x * s0); pa[1] = to_tf32(ra[it].y * s1);
                pa[2] = to_tf32(ra[it].z * s2); pa[3] = to_tf32(ra[it].w * s3);
            }
            #pragma unroll
            for (int it = 0; it < 4; it++) {
                float* pb = Bd + (rb + 32 * it) * 36 + k4;
                pb[0] = to_tf32(rbv[it].x); pb[1] = to_tf32(rbv[it].y);
                pb[2] = to_tf32(rbv[it].z); pb[3] = to_tf32(rbv[it].w);
            }
            __syncthreads();
        }
    }

    float* outp = Out + (size_t)f * NTOK * DINV;
    #pragma unroll
    for (int mt = 0; mt < 2; mt++) {
        int m0 = bm0 + wm * 32 + mt * 16 + gid;
        #pragma unroll
        for (int nt = 0; nt < 4; nt++) {
            int j = bn0 + wn * 32 + nt * 8 + tig * 2;
            float b0 = sm[H64_BIAS + wn * 32 + nt * 8 + tig * 2];
            float b1 = sm[H64_BIAS + wn * 32 + nt * 8 + tig * 2 + 1];
            float2 v0 = {d[mt][nt][0] + b0, d[mt][nt][1] + b1};
            float2 v1 = {d[mt][nt][2] + b0, d[mt][nt][3] + b1};
            *(float2*)(outp + (size_t)m0 * 512 + j)       = v0;
            *(float2*)(outp + (size_t)(m0 + 8) * 512 + j) = v1;
        }
    }
}

// ============================================================
// attention: cp.async double-buffered K/V, fused row-max, vector softmax
// smem: S 0 (32x1036) | QS 33152 | KV0 35328 | KV1 44032 | CROW 52736
//       RMAX 52864 | INV2 52992 | total 53024 floats (~207KB)
// ============================================================
#define SSTR    1036
#define AO_QS   33152
#define AO_KV0  35328
#define AO_KV1  44032
#define AO_CROW 52736
#define AO_RMAX 52864
#define AO_INV2 52992
#define ATTN_SMEM_FLOATS 53024

__global__ __launch_bounds__(256) void attn_kernel(const float* __restrict__ cin)
{
    extern __shared__ float sm[];
    float* S    = sm;
    float* Qs   = sm + AO_QS;
    float* crow = sm + AO_CROW;
    float* rmax = sm + AO_RMAX;
    float* inv2 = sm + AO_INV2;

    const int tid = threadIdx.x;
    const int warp = tid >> 5, lane = tid & 31;
    const int gid = lane >> 2, tig = lane & 3;
    const int n0  = blockIdx.x * 32;
    const int hf  = blockIdx.y;
    const int h   = hf >> 2, f = hf & 3;
    const size_t hb = (size_t)hf * NTOK * HDV;

    uint32_t sb  = smem_u32(sm);
    uint32_t kv0 = sb + AO_KV0 * 4;
    uint32_t kv1 = sb + AO_KV1 * 4;
    const float* Kp = g_k + hb;
    const float* Vp = g_v + hb;

    // prefetch K tile 0
    stage_kv(kv0, Kp, tid);
    CP_COMMIT();

    // Q block (already tf32)
    for (int i = tid; i < 512; i += 256) {
        int r = i >> 4, c4 = (i & 15) << 2;
        *(float4*)&Qs[r * 68 + c4] =
            *(const float4*)(g_q + hb + (size_t)(n0 + r) * HDV + c4);
    }
    if (tid < 128) crow[tid] = cin[(tid >> 5) * NTOK + n0 + (tid & 31)];
    __syncthreads();

    const int rg = warp & 1;
    const int cg = warp >> 1;

    uint32_t aq0[8], aq1[8], aq2[8], aq3[8];
    {
        const float* q0 = Qs + (rg * 16 + gid) * 68;
        const float* q1 = Qs + (rg * 16 + gid + 8) * 68;
        #pragma unroll
        for (int k0 = 0; k0 < 8; k0++) {
            aq0[k0] = __float_as_uint(q0[k0 * 8 + tig]);
            aq1[k0] = __float_as_uint(q1[k0 * 8 + tig]);
            aq2[k0] = __float_as_uint(q0[k0 * 8 + tig + 4]);
            aq3[k0] = __float_as_uint(q1[k0 * 8 + tig + 4]);
        }
    }

    float smax0 = -1e30f, smax1 = -1e30f;

    // ---- scores, double-buffered ----
    for (int mt = 0; mt < 8; mt++) {
        if (mt < 7) {
            stage_kv((mt & 1) ? kv0 : kv1, Kp + (mt + 1) * 8192, tid);
            CP_COMMIT();
            CP_WAIT1();
        } else {
            CP_WAIT0();
        }
        __syncthreads();
        const float* KB = sm + ((mt & 1) ? AO_KV1 : AO_KV0);

        float sacc[4][4];
        #pragma unroll
        for (int nt = 0; nt < 4; nt++)
            #pragma unroll
            for (int q = 0; q < 4; q++) sacc[nt][q] = 0.f;
        #pragma unroll
        for (int k0 = 0; k0 < 8; k0++) {
            #pragma unroll
            for (int nt = 0; nt < 4; nt++) {
                const float* p = KB + (cg * 32 + nt * 8 + gid) * 68 + k0 * 8;
                mma_tf32(sacc[nt], aq0[k0], aq1[k0], aq2[k0], aq3[k0],
                         __float_as_uint(p[tig]), __float_as_uint(p[tig + 4]));
            }
        }
        int row0 = rg * 16 + gid;
        #pragma unroll
        for (int nt = 0; nt < 4; nt++) {
            smax0 = fmaxf(smax0, fmaxf(sacc[nt][0], sacc[nt][1]));
            smax1 = fmaxf(smax1, fmaxf(sacc[nt][2], sacc[nt][3]));
            int col = mt * 128 + cg * 32 + nt * 8 + tig * 2;
            *(float2*)&S[row0 * SSTR + col]       = make_float2(sacc[nt][0], sacc[nt][1]);
            *(float2*)&S[(row0 + 8) * SSTR + col] = make_float2(sacc[nt][2], sacc[nt][3]);
        }
        __syncthreads();
    }

    // row-max partials (reduce over tig quad)
    smax0 = fmaxf(smax0, __shfl_xor_sync(0xffffffffu, smax0, 1));
    smax0 = fmaxf(smax0, __shfl_xor_sync(0xffffffffu, smax0, 2));
    smax1 = fmaxf(smax1, __shfl_xor_sync(0xffffffffu, smax1, 1));
    smax1 = fmaxf(smax1, __shfl_xor_sync(0xffffffffu, smax1, 2));
    if (tig == 0) {
        rmax[(rg * 16 + gid) * 4 + cg]     = smax0;
        rmax[(rg * 16 + gid + 8) * 4 + cg] = smax1;
    }

    // prefetch V tile 0 (overlaps softmax)
    stage_kv(kv0, Vp, tid);
    CP_COMMIT();
    __syncthreads();

    // ---- double softmax (warp -> 4 rows) ----
    {
        const float4* cT = (const float4*)g_callT;
        int r0 = warp * 4;
        float cr[4][4];
        #pragma unroll
        for (int rr = 0; rr < 4; rr++)
            #pragma unroll
            for (int ff = 0; ff < 4; ff++) cr[rr][ff] = crow[ff * 32 + r0 + rr];

        float mx[4], s1[4], um[4];
        #pragma unroll
        for (int rr = 0; rr < 4; rr++) {
            float4 m4 = *(float4*)&rmax[(r0 + rr) * 4];
            mx[rr] = fmaxf(fmaxf(m4.x, m4.y), fmaxf(m4.z, m4.w));
            s1[rr] = 0.f; um[rr] = 0.f;
        }

        #pragma unroll 2
        for (int i = 0; i < 8; i++) {
            int c = i * 128 + lane * 4;
            float4 w0 = cT[c], w1 = cT[c + 1], w2 = cT[c + 2], w3 = cT[c + 3];
            #pragma unroll
            for (int rr = 0; rr < 4; rr++) {
                float4 v = *(float4*)&S[(r0 + rr) * SSTR + c];
                float e0 = __expf(v.x - mx[rr]);
                float e1 = __expf(v.y - mx[rr]);
                float e2 = __expf(v.z - mx[rr]);
                float e3 = __expf(v.w - mx[rr]);
                float p0 = cr[rr][0] * w0.x + cr[rr][1] * w0.y + cr[rr][2] * w0.z + cr[rr][3] * w0.w;
                float p1 = cr[rr][0] * w1.x + cr[rr][1] * w1.y + cr[rr][2] * w1.z + cr[rr][3] * w1.w;
                float p2 = cr[rr][0] * w2.x + cr[rr][1] * w2.y + cr[rr][2] * w2.z + cr[rr][3] * w2.w;
                float p3 = cr[rr][0] * w3.x + cr[rr][1] * w3.y + cr[rr][2] * w3.z + cr[rr][3] * w3.w;
                float u0 = e0 * p0, u1 = e1 * p1, u2 = e2 * p2, u3 = e3 * p3;
                s1[rr] += (e0 + e1) + (e2 + e3);
                um[rr] = fmaxf(um[rr], fmaxf(fmaxf(u0, u1), fmaxf(u2, u3)));
                *(float4*)&S[(r0 + rr) * SSTR + c] = make_float4(u0, u1, u2, u3);
            }
        }
        #pragma unroll
        for (int rr = 0; rr < 4; rr++) {
            #pragma unroll
            for (int o = 16; o; o >>= 1) {
                s1[rr] += __shfl_xor_sync(0xffffffffu, s1[rr], o);
                um[rr]  = fmaxf(um[rr], __shfl_xor_sync(0xffffffffu, um[rr], o));
            }
        }
        float inv1[4], m2[4], s2[4];
        #pragma unroll
        for (int rr = 0; rr < 4; rr++) {
            inv1[rr] = 1.f / s1[rr];
            m2[rr] = um[rr] * inv1[rr];
            s2[rr] = 0.f;
        }
        #pragma unroll 2
        for (int i = 0; i < 8; i++) {
            int c = i * 128 + lane * 4;
            #pragma unroll
            for (int rr = 0; rr < 4; rr++) {
                float4 u = *(float4*)&S[(r0 + rr) * SSTR + c];
                float p0 = __expf(u.x * inv1[rr] - m2[rr]);
                float p1 = __expf(u.y * inv1[rr] - m2[rr]);
                float p2 = __expf(u.z * inv1[rr] - m2[rr]);
                float p3 = __expf(u.w * inv1[rr] - m2[rr]);
                s2[rr] += (p0 + p1) + (p2 + p3);
                *(float4*)&S[(r0 + rr) * SSTR + c] =
                    make_float4(to_tf32(p0), to_tf32(p1), to_tf32(p2), to_tf32(p3));
            }
        }
        #pragma unroll
        for (int rr = 0; rr < 4; rr++) {
            #pragma unroll
            for (int o = 16; o; o >>= 1) s2[rr] += __shfl_xor_sync(0xffffffffu, s2[rr], o);
        }
        if (lane == 0) {
            #pragma unroll
            for (int rr = 0; rr < 4; rr++) inv2[r0 + rr] = 1.f / s2[rr];
        }
    }
    __syncthreads();

    // ---- PV, double-buffered ----
    const int cg2 = warp >> 1;
    float o[2][4];
    #pragma unroll
    for (int nt = 0; nt < 2; nt++)
        #pragma unroll
        for (int q = 0; q < 4; q++) o[nt][q] = 0.f;

    for (int mt = 0; mt < 8; mt++) {
        if (mt < 7) {
            stage_kv((mt & 1) ? kv0 : kv1, Vp + (mt + 1) * 8192, tid);
            CP_COMMIT();
            CP_WAIT1();
        } else {
            CP_WAIT0();
        }
        __syncthreads();
        const float* VB = sm + ((mt & 1) ? AO_KV1 : AO_KV0);
        const float* Sr0 = S + (rg * 16 + gid) * SSTR + mt * 128;
        const float* Sr1 = Sr0 + 8 * SSTR;
        #pragma unroll
        for (int k0 = 0; k0 < 16; k0++) {
            uint32_t a0 = __float_as_uint(Sr0[k0 * 8 + tig]);
            uint32_t a1 = __float_as_uint(Sr1[k0 * 8 + tig]);
            uint32_t a2 = __float_as_uint(Sr0[k0 * 8 + tig + 4]);
            uint32_t a3 = __float_as_uint(Sr1[k0 * 8 + tig + 4]);
            #pragma unroll
            for (int nt = 0; nt < 2; nt++) {
                const float* p = VB + (k0 * 8 + tig) * 68 + cg2 * 16 + nt * 8 + gid;
                mma_tf32(o[nt], a0, a1, a2, a3,
                         __float_as_uint(p[0]), __float_as_uint(p[4 * 68]));
            }
        }
        __syncthreads();
    }

    {
        int r0e = rg * 16 + gid;
        float isa = inv2[r0e], isb = inv2[r0e + 8];
        float* yp0 = g_yhat + (size_t)f * NTOK * DINV + (size_t)(n0 + r0e) * DINV + h * HDV;
        float* yp1 = yp0 + 8 * DINV;
        #pragma unroll
        for (int nt = 0; nt < 2; nt++) {
            int dc = cg2 * 16 + nt * 8 + tig * 2;
            *(float2*)(yp0 + dc) = make_float2(o[nt][0] * isa, o[nt][1] * isa);
            *(float2*)(yp1 + dc) = make_float2(o[nt][2] * isb, o[nt][3] * isb);
        }
    }
}

// ============================================================
extern "C" void kernel_launch(void* const* d_in, const int* in_sizes, int n_in,
                              void* d_out, int out_size)
{
    const float* x      = (const float*)d_in[0];
    const float* compat = (const float*)d_in[1];
    const float* code   = (const float*)d_in[2];
    const float* wc     = (const float*)d_in[3];
    const float* Wqkv   = (const float*)d_in[4];
    const float* bqkv   = (const float*)d_in[5];
    const float* Wproj  = (const float*)d_in[6];
    const float* bproj  = (const float*)d_in[7];
    const float* lnqg   = (const float*)d_in[8];
    const float* lnqb   = (const float*)d_in[9];
    const float* lnpg   = (const float*)d_in[10];
    const float* lnpb   = (const float*)d_in[11];
    float* out = (float*)d_out;

    cudaFuncSetAttribute(attn_kernel,
                         cudaFuncAttributeMaxDynamicSharedMemorySize, ATTN_SMEM_FLOATS * 4);
    cudaFuncSetAttribute(gemm_qkv,
                         cudaFuncAttributeMaxDynamicSharedMemorySize, GEMM_SMEM_FLOATS * 4);
    cudaFuncSetAttribute(gemm_proj,
                         cudaFuncAttributeMaxDynamicSharedMemorySize, H64_FLOATS * 4);

    code_mod_kernel<<<1, 512>>>(wc, code, lnqg, lnqb, lnpg, lnpb);
    prep_callT<<<4, 256>>>(compat);
    gemm_qkv<<<dim3(12, 8, 4), 256, GEMM_SMEM_FLOATS * 4>>>(x, Wqkv, bqkv);
    attn_kernel<<<dim3(32, 32), 256, ATTN_SMEM_FLOATS * 4>>>(compat);
    gemm_proj<<<dim3(4, 16, 4), 256, H64_FLOATS * 4>>>(Wproj, bproj, out);
}